// round 12
// baseline (speedup 1.0000x reference)
#include <cuda_runtime.h>
#include <cuda_fp16.h>
#include <cstdint>

#define N_NODES 50000
#define E_EDGES 800000
#define DD 128
#define GG 256
#define CC 16
#define NLAYERS 4   // L-1 GIN layers
#define BN_EPS 1e-5f
#define POOL_ROWS 64
#define MTILES ((N_NODES + 127) / 128)   // 391
#define SCAN_BLOCKS ((N_NODES + 1023) / 1024)  // 49

// ---------------- device scratch (no allocation allowed) ----------------
__device__ __half g_z1h[(size_t)N_NODES * DD];     // z1 pre-BN1 (fp16)
__device__ __half g_feath[(size_t)N_NODES * DD];   // x / z2 gather operand (fp16)
__device__ __half g_wh[8 * DD * DD];               // transposed fp16 weights [n][k]
__device__ float g_gp[5 * GG * DD];                // per-layer graph pools
__device__ float g_stats[NLAYERS * 2 * 2 * DD];    // sums / sumsq per (layer,bn)
__device__ int   g_counts[N_NODES];
__device__ int   g_rowptr[N_NODES + 1];
__device__ int   g_cursor[N_NODES];
__device__ int   g_srcsorted[E_EDGES];
__device__ int   g_blocksums[SCAN_BLOCKS];

// ================= warp-MMA helpers (portable, sm_80+) =================
__device__ __forceinline__ uint32_t smem_u32(const void* p) {
    uint32_t a;
    asm("{ .reg .u64 t; cvta.to.shared.u64 t, %1; cvt.u32.u64 %0, t; }" : "=r"(a) : "l"(p));
    return a;
}
__device__ __forceinline__ void ldm4(uint32_t* r, uint32_t addr) {
    asm volatile("ldmatrix.sync.aligned.m8n8.x4.shared.b16 {%0,%1,%2,%3}, [%4];"
        : "=r"(r[0]), "=r"(r[1]), "=r"(r[2]), "=r"(r[3]) : "r"(addr));
}
__device__ __forceinline__ void mma16816h(float* d, const uint32_t* a, const uint32_t* b) {
    asm volatile("mma.sync.aligned.m16n8k16.row.col.f32.f16.f16.f32 "
        "{%0,%1,%2,%3}, {%4,%5,%6,%7}, {%8,%9}, {%0,%1,%2,%3};"
        : "+f"(d[0]), "+f"(d[1]), "+f"(d[2]), "+f"(d[3])
        : "r"(a[0]), "r"(a[1]), "r"(a[2]), "r"(a[3]), "r"(b[0]), "r"(b[1]));
}
__device__ __forceinline__ uint32_t sw(int row, int c8) {
    return (uint32_t)(row * 128 + ((c8 ^ (row & 7)) * 16));
}
__device__ __forceinline__ void cp16(uint32_t dst, const void* src) {
    asm volatile("cp.async.cg.shared.global [%0], [%1], 16;" :: "r"(dst), "l"(src));
}
__device__ __forceinline__ float4 bnrelu4(float4 v, float4 sc, float4 sh) {
    v.x = fmaxf(0.f, fmaf(sc.x, v.x, sh.x));
    v.y = fmaxf(0.f, fmaf(sc.y, v.y, sh.y));
    v.z = fmaxf(0.f, fmaf(sc.z, v.z, sh.z));
    v.w = fmaxf(0.f, fmaf(sc.w, v.w, sh.w));
    return v;
}
__device__ __forceinline__ float4 ldh4(const __half* p) {
    uint2 u = *(const uint2*)p;
    float2 f0 = __half22float2(*(__half2*)&u.x);
    float2 f1 = __half22float2(*(__half2*)&u.y);
    return make_float4(f0.x, f0.y, f1.x, f1.y);
}
__device__ __forceinline__ uint32_t pkh2(float a, float b) {
    __half2 h = __floats2half2_rn(a, b);
    return *(uint32_t*)&h;
}

// ---------------- utility: zero scratch ----------------
__global__ void zero_kernel(float* a, int na, float* b, int nb, int* c, int nc) {
    int i = blockIdx.x * blockDim.x + threadIdx.x;
    int stride = gridDim.x * blockDim.x;
    for (int j = i; j < na; j += stride) a[j] = 0.f;
    for (int j = i; j < nb; j += stride) b[j] = 0.f;
    for (int j = i; j < nc; j += stride) c[j] = 0;
}

// ---------------- fp32 -> fp16 convert (x into gather buffer) ----------------
__global__ void tohalf_kernel(const float* __restrict__ in, __half* __restrict__ out) {
    int i = blockIdx.x * blockDim.x + threadIdx.x;   // float4 index
    if (i < N_NODES * 32) {
        float4 v = ((const float4*)in)[i];
        uint2 u;
        u.x = pkh2(v.x, v.y);
        u.y = pkh2(v.z, v.w);
        ((uint2*)out)[i] = u;
    }
}

// ---------------- CSR build ----------------
__global__ void count_kernel(const int* __restrict__ edst, int* counts) {
    int e = blockIdx.x * blockDim.x + threadIdx.x;
    if (e < E_EDGES) atomicAdd(&counts[edst[e]], 1);
}

__global__ void scan_pass1(const int* __restrict__ counts, int* __restrict__ blocksums) {
    __shared__ int ws[8];
    int tid = threadIdx.x, lane = tid & 31, warp = tid >> 5;
    int base = blockIdx.x * 1024 + tid * 4;
    int4 v = make_int4(0, 0, 0, 0);
    if (base < N_NODES) v = *(const int4*)(counts + base);
    int s = v.x + v.y + v.z + v.w;
    #pragma unroll
    for (int off = 16; off; off >>= 1) s += __shfl_xor_sync(0xffffffffu, s, off);
    if (lane == 0) ws[warp] = s;
    __syncthreads();
    if (tid == 0) {
        int t = 0;
        #pragma unroll
        for (int w = 0; w < 8; w++) t += ws[w];
        blocksums[blockIdx.x] = t;
    }
}

__global__ void scan_pass2(int* __restrict__ blocksums, int* __restrict__ rowptr) {
    int run = 0;
    for (int i = 0; i < SCAN_BLOCKS; i++) {
        int v = blocksums[i];
        blocksums[i] = run;
        run += v;
    }
    rowptr[N_NODES] = run;
}

__global__ void scan_pass3(const int* __restrict__ counts, const int* __restrict__ blocksums,
                           int* __restrict__ rowptr, int* __restrict__ cursor) {
    __shared__ int ws[8];
    int tid = threadIdx.x, lane = tid & 31, warp = tid >> 5;
    int base = blockIdx.x * 1024 + tid * 4;
    int4 v = make_int4(0, 0, 0, 0);
    if (base < N_NODES) v = *(const int4*)(counts + base);
    int t = v.x + v.y + v.z + v.w;
    int x = t;
    #pragma unroll
    for (int off = 1; off < 32; off <<= 1) {
        int y = __shfl_up_sync(0xffffffffu, x, off);
        if (lane >= off) x += y;
    }
    if (lane == 31) ws[warp] = x;
    __syncthreads();
    if (warp == 0 && lane < 8) {
        int s = ws[lane];
        #pragma unroll
        for (int off = 1; off < 8; off <<= 1) {
            int y = __shfl_up_sync(0x000000ffu, s, off);
            if (lane >= off) s += y;
        }
        ws[lane] = s;
    }
    __syncthreads();
    int excl = (x - t) + (warp ? ws[warp - 1] : 0) + blocksums[blockIdx.x];
    if (base < N_NODES) {
        int4 rp;
        rp.x = excl;
        rp.y = excl + v.x;
        rp.z = rp.y + v.y;
        rp.w = rp.z + v.z;
        *(int4*)(rowptr + base) = rp;
        *(int4*)(cursor + base) = rp;
    }
}

__global__ void fill_kernel(const int* __restrict__ esrc, const int* __restrict__ edst,
                            int* cursor, int* srcsorted) {
    int e = blockIdx.x * blockDim.x + threadIdx.x;
    if (e < E_EDGES) {
        int pos = atomicAdd(&cursor[edst[e]], 1);
        srcsorted[pos] = esrc[e];
    }
}

// ---------------- weight prep: transpose + fp16 ----------------
__global__ void wprep_kernel(const float* __restrict__ W1, const float* __restrict__ W2,
                             __half* __restrict__ wh) {
    int m = blockIdx.x;
    int kb = blockIdx.y;
    int n = threadIdx.x;
    const float* W = (m < 4) ? (W1 + (size_t)m * DD * DD) : (W2 + (size_t)(m - 4) * DD * DD);
    for (int k = kb * 16; k < kb * 16 + 16; k++) {
        float w = W[(size_t)k * DD + n];
        wh[((size_t)m * DD + n) * DD + k] = __float2half(w);
    }
}

#define SM_A 0
#define SM_W 32768                  // + ch*16384
#define SM_TOTAL 65536

// ======== FUSED spmm + GEMM1 ========
// Phase 1 (gather): each warp computes 16 pooled rows of this block's 128-row tile
//   directly into the swizzled smem A tile (fp16), applying BN(feat)+ReLU for l>0,
//   the (1+eps) self term, and per-graph pooling atomics (sorted gid run-length).
// Phase 2 (MMA): A @ W1 + b1 -> z1h, fused column stats. W cp.async overlaps phase 1.
template<bool APPLY_BN>
__global__ __launch_bounds__(256, 2) void spmm_gemm1_kernel(
    const __half* __restrict__ feat,
    const float* __restrict__ stats_in, const float* __restrict__ gam,
    const float* __restrict__ bet,
    const int* __restrict__ rowptr, const int* __restrict__ srcs,
    const float* __restrict__ eps, int l, const int* __restrict__ gid,
    const __half* __restrict__ Wh, const float* __restrict__ bias,
    __half* __restrict__ CoutH, float* __restrict__ stats_out,
    float* __restrict__ gp) {
    extern __shared__ char smem[];
    uint32_t sb = smem_u32(smem);
    int tid = threadIdx.x, wid = tid >> 5, lane = tid & 31;
    int wm = wid >> 2, wn = wid & 3;
    int row0 = blockIdx.x * 128;

    // W loads via cp.async: overlap with the gather phase
    #pragma unroll
    for (int i = 0; i < 8; i++) {
        int slot = i * 256 + tid;
        int ch = slot >> 10;
        int idx = slot & 1023;
        int row = idx >> 3, c8 = idx & 7;
        cp16(sb + SM_W + ch * 16384 + sw(row, c8),
             Wh + (size_t)row * DD + ch * 64 + c8 * 8);
    }
    asm volatile("cp.async.commit_group;" ::: "memory");

    // ---- Phase 1: gather into smem A tile ----
    {
        int c = lane * 4;                               // global column base
        int ch = lane >> 4;                             // chunk 0/1
        int c8l = (lane >> 1) & 7;                      // 16B chunk within row
        uint32_t abase = (uint32_t)(SM_A + ch * 16384 + (lane & 1) * 8);
        float scale = 1.0f + __ldg(eps + l);

        float4 sc, sh;
        if (APPLY_BN) {
            const float invN = 1.0f / (float)N_NODES;
            float4 sm = *(const float4*)(stats_in + c);
            float4 sq = *(const float4*)(stats_in + DD + c);
            float4 gg = *(const float4*)(gam + c);
            float4 bb = *(const float4*)(bet + c);
            float m0 = sm.x * invN, m1 = sm.y * invN, m2 = sm.z * invN, m3 = sm.w * invN;
            sc.x = gg.x * rsqrtf(sq.x * invN - m0 * m0 + BN_EPS);
            sc.y = gg.y * rsqrtf(sq.y * invN - m1 * m1 + BN_EPS);
            sc.z = gg.z * rsqrtf(sq.z * invN - m2 * m2 + BN_EPS);
            sc.w = gg.w * rsqrtf(sq.w * invN - m3 * m3 + BN_EPS);
            sh.x = bb.x - sc.x * m0; sh.y = bb.y - sc.y * m1;
            sh.z = bb.z - sc.z * m2; sh.w = bb.w - sc.w * m3;
        }

        int nodebase = row0 + wid * 16;
        bool anyvalid = (nodebase < N_NODES);
        float4 pacc = make_float4(0.f, 0.f, 0.f, 0.f);
        int curg = anyvalid ? __ldg(gid + nodebase) : 0;

        for (int i = 0; i < 16; i++) {
            int node = nodebase + i;
            int row = wid * 16 + i;
            char* adst = smem + abase + sw(row, c8l);
            if (node < N_NODES) {
                float4 hv = ldh4(feat + (size_t)node * DD + c);
                if (APPLY_BN) hv = bnrelu4(hv, sc, sh);

                int gcur = __ldg(gid + node);
                if (gcur != curg) {
                    float* gpd = gp + (size_t)curg * DD + c;
                    atomicAdd(gpd + 0, pacc.x); atomicAdd(gpd + 1, pacc.y);
                    atomicAdd(gpd + 2, pacc.z); atomicAdd(gpd + 3, pacc.w);
                    pacc = make_float4(0.f, 0.f, 0.f, 0.f);
                    curg = gcur;
                }
                pacc.x += hv.x; pacc.y += hv.y; pacc.z += hv.z; pacc.w += hv.w;

                float4 acc;
                acc.x = scale * hv.x; acc.y = scale * hv.y;
                acc.z = scale * hv.z; acc.w = scale * hv.w;

                int s = __ldg(rowptr + node), e = __ldg(rowptr + node + 1);
                int j = s;
                for (; j + 3 < e; j += 4) {
                    int s0 = __ldg(srcs + j + 0);
                    int s1 = __ldg(srcs + j + 1);
                    int s2 = __ldg(srcs + j + 2);
                    int s3 = __ldg(srcs + j + 3);
                    float4 v0 = ldh4(feat + (size_t)s0 * DD + c);
                    float4 v1 = ldh4(feat + (size_t)s1 * DD + c);
                    float4 v2 = ldh4(feat + (size_t)s2 * DD + c);
                    float4 v3 = ldh4(feat + (size_t)s3 * DD + c);
                    if (APPLY_BN) {
                        v0 = bnrelu4(v0, sc, sh); v1 = bnrelu4(v1, sc, sh);
                        v2 = bnrelu4(v2, sc, sh); v3 = bnrelu4(v3, sc, sh);
                    }
                    acc.x += v0.x + v1.x + v2.x + v3.x;
                    acc.y += v0.y + v1.y + v2.y + v3.y;
                    acc.z += v0.z + v1.z + v2.z + v3.z;
                    acc.w += v0.w + v1.w + v2.w + v3.w;
                }
                for (; j < e; j++) {
                    int s0 = __ldg(srcs + j);
                    float4 v0 = ldh4(feat + (size_t)s0 * DD + c);
                    if (APPLY_BN) v0 = bnrelu4(v0, sc, sh);
                    acc.x += v0.x; acc.y += v0.y; acc.z += v0.z; acc.w += v0.w;
                }
                uint2 u;
                u.x = pkh2(acc.x, acc.y);
                u.y = pkh2(acc.z, acc.w);
                *(uint2*)adst = u;
            } else {
                *(uint2*)adst = make_uint2(0u, 0u);
            }
        }
        if (anyvalid) {
            float* gpd = gp + (size_t)curg * DD + c;
            atomicAdd(gpd + 0, pacc.x); atomicAdd(gpd + 1, pacc.y);
            atomicAdd(gpd + 2, pacc.z); atomicAdd(gpd + 3, pacc.w);
        }
    }
    asm volatile("cp.async.wait_group 0;" ::: "memory");
    __syncthreads();

    // ---- Phase 2: MMA ----
    float acc[4][4][4];
    #pragma unroll
    for (int i = 0; i < 4; i++)
        #pragma unroll
        for (int j = 0; j < 4; j++)
            #pragma unroll
            for (int k = 0; k < 4; k++) acc[i][j][k] = 0.f;

    int frow = ((lane >> 3) & 1) * 8 + (lane & 7);
    int fc8base = (lane >> 4);

    #pragma unroll
    for (int ch = 0; ch < 2; ch++) {
        uint32_t ab = sb + SM_A + ch * 16384;
        uint32_t wb = sb + SM_W + ch * 16384;
        #pragma unroll
        for (int ks = 0; ks < 4; ks++) {
            int c8 = ks * 2 + fc8base;
            uint32_t bh[4][2];
            #pragma unroll
            for (int np = 0; np < 2; np++) {
                int n = wn * 32 + np * 16 + frow;
                uint32_t t[4];
                ldm4(t, wb + sw(n, c8));
                bh[np * 2 + 0][0] = t[0]; bh[np * 2 + 1][0] = t[1];
                bh[np * 2 + 0][1] = t[2]; bh[np * 2 + 1][1] = t[3];
            }
            #pragma unroll
            for (int mt = 0; mt < 4; mt++) {
                int r = wm * 64 + mt * 16 + frow;
                uint32_t ah[4];
                ldm4(ah, ab + sw(r, c8));
                #pragma unroll
                for (int nt = 0; nt < 4; nt++)
                    mma16816h(acc[mt][nt], ah, bh[nt]);
            }
        }
    }

    // ---- epilogue: bias, fp16 store, fused column stats ----
    float st[4][4];
    #pragma unroll
    for (int nt = 0; nt < 4; nt++)
        #pragma unroll
        for (int k = 0; k < 4; k++) st[nt][k] = 0.f;

    #pragma unroll
    for (int nt = 0; nt < 4; nt++) {
        int col = wn * 32 + nt * 8 + (lane & 3) * 2;
        float2 bs = *(const float2*)(bias + col);
        #pragma unroll
        for (int mt = 0; mt < 4; mt++) {
            int r0g = row0 + wm * 64 + mt * 16 + (lane >> 2);
            float v0 = acc[mt][nt][0] + bs.x;
            float v1 = acc[mt][nt][1] + bs.y;
            float v2 = acc[mt][nt][2] + bs.x;
            float v3 = acc[mt][nt][3] + bs.y;
            if (r0g < N_NODES) {
                *(uint32_t*)(CoutH + (size_t)r0g * DD + col) = pkh2(v0, v1);
                st[nt][0] += v0; st[nt][1] += v1;
                st[nt][2] = fmaf(v0, v0, st[nt][2]);
                st[nt][3] = fmaf(v1, v1, st[nt][3]);
            }
            if (r0g + 8 < N_NODES) {
                *(uint32_t*)(CoutH + (size_t)(r0g + 8) * DD + col) = pkh2(v2, v3);
                st[nt][0] += v2; st[nt][1] += v3;
                st[nt][2] = fmaf(v2, v2, st[nt][2]);
                st[nt][3] = fmaf(v3, v3, st[nt][3]);
            }
        }
    }
    #pragma unroll
    for (int nt = 0; nt < 4; nt++) {
        #pragma unroll
        for (int off = 4; off < 32; off <<= 1) {
            #pragma unroll
            for (int k = 0; k < 4; k++)
                st[nt][k] += __shfl_xor_sync(0xffffffffu, st[nt][k], off);
        }
    }
    if (lane < 4) {
        #pragma unroll
        for (int nt = 0; nt < 4; nt++) {
            int col = wn * 32 + nt * 8 + lane * 2;
            atomicAdd(stats_out + col,          st[nt][0]);
            atomicAdd(stats_out + col + 1,      st[nt][1]);
            atomicAdd(stats_out + DD + col,     st[nt][2]);
            atomicAdd(stats_out + DD + col + 1, st[nt][3]);
        }
    }
}

// ---------------- GEMM2: z2h = BN1(z1h)+ReLU @ W2 + b2, fused stats ----------------
__global__ __launch_bounds__(256, 2) void mma_gemm2_kernel(
    const __half* __restrict__ A,
    const float* __restrict__ stats_in, const float* __restrict__ gam,
    const float* __restrict__ bet,
    const __half* __restrict__ Wh,
    const float* __restrict__ bias, __half* __restrict__ CoutH,
    float* __restrict__ stats_out) {
    extern __shared__ char smem[];
    __shared__ float scs[2 * DD];
    uint32_t sb = smem_u32(smem);
    int tid = threadIdx.x, wid = tid >> 5, lane = tid & 31;
    int wm = wid >> 2, wn = wid & 3;
    int row0 = blockIdx.x * 128;

    #pragma unroll
    for (int i = 0; i < 8; i++) {
        int slot = i * 256 + tid;
        int ch = slot >> 10;
        int idx = slot & 1023;
        int row = idx >> 3, c8 = idx & 7;
        cp16(sb + SM_W + ch * 16384 + sw(row, c8),
             Wh + (size_t)row * DD + ch * 64 + c8 * 8);
    }
    asm volatile("cp.async.commit_group;" ::: "memory");

    if (tid < DD) {
        const float invN = 1.0f / (float)N_NODES;
        float mean = __ldg(stats_in + tid) * invN;
        float var = __ldg(stats_in + DD + tid) * invN - mean * mean;
        float sc = __ldg(gam + tid) * rsqrtf(var + BN_EPS);
        scs[tid] = sc;
        scs[DD + tid] = __ldg(bet + tid) - sc * mean;
    }
    __syncthreads();
    #pragma unroll
    for (int i = 0; i < 8; i++) {
        int slot = i * 256 + tid;
        int ch = slot >> 10;
        int idx = slot & 1023;
        int row = idx >> 3, c8 = idx & 7;
        int gr = row0 + row;
        int col = ch * 64 + c8 * 8;
        float4 va = make_float4(0.f, 0.f, 0.f, 0.f), vb = va;
        if (gr < N_NODES) {
            const __half* ap = A + (size_t)gr * DD + col;
            va = ldh4(ap);
            vb = ldh4(ap + 4);
        }
        float4 s0 = *(const float4*)(scs + col);
        float4 s1 = *(const float4*)(scs + col + 4);
        float4 t0 = *(const float4*)(scs + DD + col);
        float4 t1 = *(const float4*)(scs + DD + col + 4);
        va = bnrelu4(va, s0, t0);
        vb = bnrelu4(vb, s1, t1);
        uint4 h;
        h.x = pkh2(va.x, va.y);
        h.y = pkh2(va.z, va.w);
        h.z = pkh2(vb.x, vb.y);
        h.w = pkh2(vb.z, vb.w);
        *(uint4*)(smem + SM_A + ch * 16384 + sw(row, c8)) = h;
    }
    asm volatile("cp.async.wait_group 0;" ::: "memory");
    __syncthreads();

    float acc[4][4][4];
    #pragma unroll
    for (int i = 0; i < 4; i++)
        #pragma unroll
        for (int j = 0; j < 4; j++)
            #pragma unroll
            for (int k = 0; k < 4; k++) acc[i][j][k] = 0.f;

    int frow = ((lane >> 3) & 1) * 8 + (lane & 7);
    int fc8base = (lane >> 4);

    #pragma unroll
    for (int ch = 0; ch < 2; ch++) {
        uint32_t ab = sb + SM_A + ch * 16384;
        uint32_t wb = sb + SM_W + ch * 16384;
        #pragma unroll
        for (int ks = 0; ks < 4; ks++) {
            int c8 = ks * 2 + fc8base;
            uint32_t bh[4][2];
            #pragma unroll
            for (int np = 0; np < 2; np++) {
                int n = wn * 32 + np * 16 + frow;
                uint32_t t[4];
                ldm4(t, wb + sw(n, c8));
                bh[np * 2 + 0][0] = t[0]; bh[np * 2 + 1][0] = t[1];
                bh[np * 2 + 0][1] = t[2]; bh[np * 2 + 1][1] = t[3];
            }
            #pragma unroll
            for (int mt = 0; mt < 4; mt++) {
                int r = wm * 64 + mt * 16 + frow;
                uint32_t ah[4];
                ldm4(ah, ab + sw(r, c8));
                #pragma unroll
                for (int nt = 0; nt < 4; nt++)
                    mma16816h(acc[mt][nt], ah, bh[nt]);
            }
        }
    }

    float st[4][4];
    #pragma unroll
    for (int nt = 0; nt < 4; nt++)
        #pragma unroll
        for (int k = 0; k < 4; k++) st[nt][k] = 0.f;

    #pragma unroll
    for (int nt = 0; nt < 4; nt++) {
        int col = wn * 32 + nt * 8 + (lane & 3) * 2;
        float2 bs = *(const float2*)(bias + col);
        #pragma unroll
        for (int mt = 0; mt < 4; mt++) {
            int r0g = row0 + wm * 64 + mt * 16 + (lane >> 2);
            float v0 = acc[mt][nt][0] + bs.x;
            float v1 = acc[mt][nt][1] + bs.y;
            float v2 = acc[mt][nt][2] + bs.x;
            float v3 = acc[mt][nt][3] + bs.y;
            if (r0g < N_NODES) {
                *(uint32_t*)(CoutH + (size_t)r0g * DD + col) = pkh2(v0, v1);
                st[nt][0] += v0; st[nt][1] += v1;
                st[nt][2] = fmaf(v0, v0, st[nt][2]);
                st[nt][3] = fmaf(v1, v1, st[nt][3]);
            }
            if (r0g + 8 < N_NODES) {
                *(uint32_t*)(CoutH + (size_t)(r0g + 8) * DD + col) = pkh2(v2, v3);
                st[nt][0] += v2; st[nt][1] += v3;
                st[nt][2] = fmaf(v2, v2, st[nt][2]);
                st[nt][3] = fmaf(v3, v3, st[nt][3]);
            }
        }
    }
    #pragma unroll
    for (int nt = 0; nt < 4; nt++) {
        #pragma unroll
        for (int off = 4; off < 32; off <<= 1) {
            #pragma unroll
            for (int k = 0; k < 4; k++)
                st[nt][k] += __shfl_xor_sync(0xffffffffu, st[nt][k], off);
        }
    }
    if (lane < 4) {
        #pragma unroll
        for (int nt = 0; nt < 4; nt++) {
            int col = wn * 32 + nt * 8 + lane * 2;
            atomicAdd(stats_out + col,          st[nt][0]);
            atomicAdd(stats_out + col + 1,      st[nt][1]);
            atomicAdd(stats_out + DD + col,     st[nt][2]);
            atomicAdd(stats_out + DD + col + 1, st[nt][3]);
        }
    }
}

// ---------------- final pool: BN2(z2)+ReLU summed per graph (fp16 z2) ----------------
__global__ void pool_final_kernel(const __half* __restrict__ z, const float* __restrict__ stats,
                                  const float* __restrict__ g, const float* __restrict__ beta,
                                  const int* __restrict__ gid, float* __restrict__ gp) {
    int tid = threadIdx.x;  // 128
    int r0 = blockIdx.x * POOL_ROWS;
    if (r0 >= N_NODES) return;
    int rend = min(r0 + POOL_ROWS, N_NODES);
    const float invN = 1.0f / (float)N_NODES;
    float mean = __ldg(stats + tid) * invN;
    float var = __ldg(stats + DD + tid) * invN - mean * mean;
    float sc = __ldg(g + tid) * rsqrtf(var + BN_EPS);
    float sh = __ldg(beta + tid) - sc * mean;
    float acc = 0.f;
    int curg = __ldg(gid + r0);
    for (int r = r0; r < rend; r++) {
        float v = __half2float(z[(size_t)r * DD + tid]);
        float hv = fmaxf(0.f, fmaf(sc, v, sh));
        int gcur = __ldg(gid + r);
        if (gcur != curg) {
            atomicAdd(gp + (size_t)curg * DD + tid, acc);
            acc = 0.f;
            curg = gcur;
        }
        acc += hv;
    }
    atomicAdd(gp + (size_t)curg * DD + tid, acc);
}

// ---------------- readout ----------------
__global__ void readout_kernel(const float* __restrict__ gp, const float* __restrict__ Wp,
                               const float* __restrict__ bp, float* __restrict__ out) {
    int g = blockIdx.x;
    int tid = threadIdx.x;  // 128
    int lane = tid & 31, warp = tid >> 5;
    float partial[CC];
    #pragma unroll
    for (int c = 0; c < CC; c++) partial[c] = 0.f;
    for (int l = 0; l < 5; l++) {
        float v = gp[((size_t)l * GG + g) * DD + tid];
        const float* w = Wp + ((size_t)l * DD + tid) * CC;
        #pragma unroll
        for (int c = 0; c < CC; c++) partial[c] = fmaf(v, __ldg(w + c), partial[c]);
    }
    __shared__ float red[4][CC];
    #pragma unroll
    for (int c = 0; c < CC; c++) {
        float v = partial[c];
        #pragma unroll
        for (int off = 16; off; off >>= 1) v += __shfl_down_sync(0xffffffffu, v, off);
        if (lane == 0) red[warp][c] = v;
    }
    __syncthreads();
    if (tid < CC) {
        float s = red[0][tid] + red[1][tid] + red[2][tid] + red[3][tid];
        float b = 0.f;
        #pragma unroll
        for (int l = 0; l < 5; l++) b += __ldg(bp + l * CC + tid);
        out[g * CC + tid] = s + b;
    }
}

// ---------------- host orchestration ----------------
extern "C" void kernel_launch(void* const* d_in, const int* in_sizes, int n_in,
                              void* d_out, int out_size) {
    const float* x     = (const float*)d_in[0];
    const float* eps   = (const float*)d_in[1];
    const float* W1    = (const float*)d_in[2];
    const float* b1    = (const float*)d_in[3];
    const float* g1    = (const float*)d_in[4];
    const float* beta1 = (const float*)d_in[5];
    const float* W2    = (const float*)d_in[6];
    const float* b2    = (const float*)d_in[7];
    const float* g2    = (const float*)d_in[8];
    const float* beta2 = (const float*)d_in[9];
    const float* Wp    = (const float*)d_in[10];
    const float* bp    = (const float*)d_in[11];
    const int* esrc    = (const int*)d_in[12];
    const int* edst    = (const int*)d_in[13];
    const int* gid     = (const int*)d_in[14];
    float* out = (float*)d_out;

    float *gp, *stats;
    __half *z1h, *feath, *wh;
    int *counts, *rowptr, *cursor, *srcsorted, *blocksums;
    cudaGetSymbolAddress((void**)&z1h, g_z1h);
    cudaGetSymbolAddress((void**)&feath, g_feath);
    cudaGetSymbolAddress((void**)&wh, g_wh);
    cudaGetSymbolAddress((void**)&gp, g_gp);
    cudaGetSymbolAddress((void**)&stats, g_stats);
    cudaGetSymbolAddress((void**)&counts, g_counts);
    cudaGetSymbolAddress((void**)&rowptr, g_rowptr);
    cudaGetSymbolAddress((void**)&cursor, g_cursor);
    cudaGetSymbolAddress((void**)&srcsorted, g_srcsorted);
    cudaGetSymbolAddress((void**)&blocksums, g_blocksums);

    cudaFuncSetAttribute(spmm_gemm1_kernel<false>,
                         cudaFuncAttributeMaxDynamicSharedMemorySize, SM_TOTAL);
    cudaFuncSetAttribute(spmm_gemm1_kernel<true>,
                         cudaFuncAttributeMaxDynamicSharedMemorySize, SM_TOTAL);
    cudaFuncSetAttribute(mma_gemm2_kernel,
                         cudaFuncAttributeMaxDynamicSharedMemorySize, SM_TOTAL);

    zero_kernel<<<256, 256>>>(gp, 5 * GG * DD, stats, NLAYERS * 2 * 2 * DD, counts, N_NODES);
    wprep_kernel<<<dim3(8, 8), 128>>>(W1, W2, wh);
    tohalf_kernel<<<(N_NODES * 32 + 255) / 256, 256>>>(x, feath);
    count_kernel<<<(E_EDGES + 255) / 256, 256>>>(edst, counts);
    scan_pass1<<<SCAN_BLOCKS, 256>>>(counts, blocksums);
    scan_pass2<<<1, 1>>>(blocksums, rowptr);
    scan_pass3<<<SCAN_BLOCKS, 256>>>(counts, blocksums, rowptr, cursor);
    fill_kernel<<<(E_EDGES + 255) / 256, 256>>>(esrc, edst, cursor, srcsorted);

    for (int l = 0; l < NLAYERS; l++) {
        float* st1 = stats + (l * 2 + 0) * 2 * DD;
        float* st2 = stats + (l * 2 + 1) * 2 * DD;

        if (l == 0) {
            spmm_gemm1_kernel<false><<<MTILES, 256, SM_TOTAL>>>(
                feath, nullptr, nullptr, nullptr, rowptr, srcsorted, eps, l, gid,
                wh + (size_t)l * DD * DD, b1 + l * DD, z1h, st1,
                gp + (size_t)l * GG * DD);
        } else {
            float* st2p = stats + ((l - 1) * 2 + 1) * 2 * DD;
            spmm_gemm1_kernel<true><<<MTILES, 256, SM_TOTAL>>>(
                feath, st2p, g2 + (l - 1) * DD, beta2 + (l - 1) * DD,
                rowptr, srcsorted, eps, l, gid,
                wh + (size_t)l * DD * DD, b1 + l * DD, z1h, st1,
                gp + (size_t)l * GG * DD);
        }
        mma_gemm2_kernel<<<MTILES, 256, SM_TOTAL>>>(
            z1h, st1, g1 + l * DD, beta1 + l * DD,
            wh + (size_t)(4 + l) * DD * DD, b2 + l * DD, feath, st2);
    }
    pool_final_kernel<<<(N_NODES + POOL_ROWS - 1) / POOL_ROWS, 128>>>(
        feath, stats + ((NLAYERS - 1) * 2 + 1) * 2 * DD,
        g2 + (NLAYERS - 1) * DD, beta2 + (NLAYERS - 1) * DD, gid,
        gp + (size_t)NLAYERS * GG * DD);
    readout_kernel<<<GG, 128>>>(gp, Wp, bp, out);
}

// round 13
// speedup vs baseline: 1.2928x; 1.2928x over previous
#include <cuda_runtime.h>
#include <cuda_fp16.h>
#include <cstdint>

#define N_NODES 50000
#define E_EDGES 800000
#define DD 128
#define GG 256
#define CC 16
#define NLAYERS 4   // L-1 GIN layers
#define BN_EPS 1e-5f
#define POOL_ROWS 64
#define MTILES ((N_NODES + 127) / 128)   // 391
#define SCAN_BLOCKS ((N_NODES + 1023) / 1024)  // 49
#define NODES_PER_WARP 4
#define SPMM_BLOCKS ((N_NODES + 8 * NODES_PER_WARP - 1) / (8 * NODES_PER_WARP))

// ---------------- device scratch (no allocation allowed) ----------------
__device__ __half g_pooledh[(size_t)N_NODES * DD]; // spmm output (fp16)
__device__ __half g_z1h[(size_t)N_NODES * DD];     // z1 pre-BN1 (fp16)
__device__ __half g_feath[(size_t)N_NODES * DD];   // x / z2 gather operand (fp16)
__device__ __half g_wh[8 * DD * DD];               // transposed fp16 weights [n][k]
__device__ float g_gp[5 * GG * DD];                // per-layer graph pools
__device__ float g_stats[NLAYERS * 2 * 2 * DD];    // sums / sumsq per (layer,bn)
__device__ int   g_counts[N_NODES];
__device__ int   g_rowptr[N_NODES + 1];
__device__ int   g_cursor[N_NODES];
__device__ int   g_srcsorted[E_EDGES];
__device__ int   g_blocksums[SCAN_BLOCKS];

// ================= warp-MMA helpers (portable, sm_80+) =================
__device__ __forceinline__ uint32_t smem_u32(const void* p) {
    uint32_t a;
    asm("{ .reg .u64 t; cvta.to.shared.u64 t, %1; cvt.u32.u64 %0, t; }" : "=r"(a) : "l"(p));
    return a;
}
__device__ __forceinline__ void ldm4(uint32_t* r, uint32_t addr) {
    asm volatile("ldmatrix.sync.aligned.m8n8.x4.shared.b16 {%0,%1,%2,%3}, [%4];"
        : "=r"(r[0]), "=r"(r[1]), "=r"(r[2]), "=r"(r[3]) : "r"(addr));
}
__device__ __forceinline__ void mma16816h(float* d, const uint32_t* a, const uint32_t* b) {
    asm volatile("mma.sync.aligned.m16n8k16.row.col.f32.f16.f16.f32 "
        "{%0,%1,%2,%3}, {%4,%5,%6,%7}, {%8,%9}, {%0,%1,%2,%3};"
        : "+f"(d[0]), "+f"(d[1]), "+f"(d[2]), "+f"(d[3])
        : "r"(a[0]), "r"(a[1]), "r"(a[2]), "r"(a[3]), "r"(b[0]), "r"(b[1]));
}
__device__ __forceinline__ uint32_t sw(int row, int c8) {
    return (uint32_t)(row * 128 + ((c8 ^ (row & 7)) * 16));
}
__device__ __forceinline__ void cp16(uint32_t dst, const void* src) {
    asm volatile("cp.async.cg.shared.global [%0], [%1], 16;" :: "r"(dst), "l"(src));
}
// guarded cp.async: zero-fill when pred false (src still a valid address)
__device__ __forceinline__ void cp16z(uint32_t dst, const void* src, bool pred) {
    int sz = pred ? 16 : 0;
    asm volatile("cp.async.cg.shared.global [%0], [%1], 16, %2;"
        :: "r"(dst), "l"(src), "r"(sz));
}
__device__ __forceinline__ float4 bnrelu4(float4 v, float4 sc, float4 sh) {
    v.x = fmaxf(0.f, fmaf(sc.x, v.x, sh.x));
    v.y = fmaxf(0.f, fmaf(sc.y, v.y, sh.y));
    v.z = fmaxf(0.f, fmaf(sc.z, v.z, sh.z));
    v.w = fmaxf(0.f, fmaf(sc.w, v.w, sh.w));
    return v;
}
__device__ __forceinline__ float4 ldh4(const __half* p) {
    uint2 u = *(const uint2*)p;
    float2 f0 = __half22float2(*(__half2*)&u.x);
    float2 f1 = __half22float2(*(__half2*)&u.y);
    return make_float4(f0.x, f0.y, f1.x, f1.y);
}
__device__ __forceinline__ uint32_t pkh2(float a, float b) {
    __half2 h = __floats2half2_rn(a, b);
    return *(uint32_t*)&h;
}

// ---------------- utility: zero scratch ----------------
__global__ void zero_kernel(float* a, int na, float* b, int nb, int* c, int nc) {
    int i = blockIdx.x * blockDim.x + threadIdx.x;
    int stride = gridDim.x * blockDim.x;
    for (int j = i; j < na; j += stride) a[j] = 0.f;
    for (int j = i; j < nb; j += stride) b[j] = 0.f;
    for (int j = i; j < nc; j += stride) c[j] = 0;
}

// ---------------- fp32 -> fp16 convert (x into gather buffer) ----------------
__global__ void tohalf_kernel(const float* __restrict__ in, __half* __restrict__ out) {
    int i = blockIdx.x * blockDim.x + threadIdx.x;   // float4 index
    if (i < N_NODES * 32) {
        float4 v = ((const float4*)in)[i];
        uint2 u;
        u.x = pkh2(v.x, v.y);
        u.y = pkh2(v.z, v.w);
        ((uint2*)out)[i] = u;
    }
}

// ---------------- CSR build ----------------
__global__ void count_kernel(const int* __restrict__ edst, int* counts) {
    int e = blockIdx.x * blockDim.x + threadIdx.x;
    if (e < E_EDGES) atomicAdd(&counts[edst[e]], 1);
}

__global__ void scan_pass1(const int* __restrict__ counts, int* __restrict__ blocksums) {
    __shared__ int ws[8];
    int tid = threadIdx.x, lane = tid & 31, warp = tid >> 5;
    int base = blockIdx.x * 1024 + tid * 4;
    int4 v = make_int4(0, 0, 0, 0);
    if (base < N_NODES) v = *(const int4*)(counts + base);
    int s = v.x + v.y + v.z + v.w;
    #pragma unroll
    for (int off = 16; off; off >>= 1) s += __shfl_xor_sync(0xffffffffu, s, off);
    if (lane == 0) ws[warp] = s;
    __syncthreads();
    if (tid == 0) {
        int t = 0;
        #pragma unroll
        for (int w = 0; w < 8; w++) t += ws[w];
        blocksums[blockIdx.x] = t;
    }
}

__global__ void scan_pass2(int* __restrict__ blocksums, int* __restrict__ rowptr) {
    int run = 0;
    for (int i = 0; i < SCAN_BLOCKS; i++) {
        int v = blocksums[i];
        blocksums[i] = run;
        run += v;
    }
    rowptr[N_NODES] = run;
}

__global__ void scan_pass3(const int* __restrict__ counts, const int* __restrict__ blocksums,
                           int* __restrict__ rowptr, int* __restrict__ cursor) {
    __shared__ int ws[8];
    int tid = threadIdx.x, lane = tid & 31, warp = tid >> 5;
    int base = blockIdx.x * 1024 + tid * 4;
    int4 v = make_int4(0, 0, 0, 0);
    if (base < N_NODES) v = *(const int4*)(counts + base);
    int t = v.x + v.y + v.z + v.w;
    int x = t;
    #pragma unroll
    for (int off = 1; off < 32; off <<= 1) {
        int y = __shfl_up_sync(0xffffffffu, x, off);
        if (lane >= off) x += y;
    }
    if (lane == 31) ws[warp] = x;
    __syncthreads();
    if (warp == 0 && lane < 8) {
        int s = ws[lane];
        #pragma unroll
        for (int off = 1; off < 8; off <<= 1) {
            int y = __shfl_up_sync(0x000000ffu, s, off);
            if (lane >= off) s += y;
        }
        ws[lane] = s;
    }
    __syncthreads();
    int excl = (x - t) + (warp ? ws[warp - 1] : 0) + blocksums[blockIdx.x];
    if (base < N_NODES) {
        int4 rp;
        rp.x = excl;
        rp.y = excl + v.x;
        rp.z = rp.y + v.y;
        rp.w = rp.z + v.z;
        *(int4*)(rowptr + base) = rp;
        *(int4*)(cursor + base) = rp;
    }
}

__global__ void fill_kernel(const int* __restrict__ esrc, const int* __restrict__ edst,
                            int* cursor, int* srcsorted) {
    int e = blockIdx.x * blockDim.x + threadIdx.x;
    if (e < E_EDGES) {
        int pos = atomicAdd(&cursor[edst[e]], 1);
        srcsorted[pos] = esrc[e];
    }
}

// ---------------- weight prep: transpose + fp16 ----------------
__global__ void wprep_kernel(const float* __restrict__ W1, const float* __restrict__ W2,
                             __half* __restrict__ wh) {
    int m = blockIdx.x;
    int kb = blockIdx.y;
    int n = threadIdx.x;
    const float* W = (m < 4) ? (W1 + (size_t)m * DD * DD) : (W2 + (size_t)(m - 4) * DD * DD);
    for (int k = kb * 16; k < kb * 16 + 16; k++) {
        float w = W[(size_t)k * DD + n];
        wh[((size_t)m * DD + n) * DD + k] = __float2half(w);
    }
}

// ---------------- fused SpMM (fp16): BN(feat) + eps-self + pooling, fp16 out ----------------
template<bool APPLY_BN>
__global__ __launch_bounds__(256) void spmm_fused_kernel(
    const __half* __restrict__ feat,
    const float* __restrict__ stats, const float* __restrict__ gam,
    const float* __restrict__ bet,
    const int* __restrict__ rowptr, const int* __restrict__ srcs,
    const float* __restrict__ eps, int l, const int* __restrict__ gid,
    __half* __restrict__ pooled, float* __restrict__ gp) {
    int lane = threadIdx.x & 31, warp = threadIdx.x >> 5;
    int node0 = (blockIdx.x * 8 + warp) * NODES_PER_WARP;
    if (node0 >= N_NODES) return;
    int nend = min(node0 + NODES_PER_WARP, N_NODES);
    int c = lane * 4;
    float scale = 1.0f + __ldg(eps + l);

    float4 sc, sh;
    if (APPLY_BN) {
        const float invN = 1.0f / (float)N_NODES;
        float4 sm = *(const float4*)(stats + c);
        float4 sq = *(const float4*)(stats + DD + c);
        float4 gg = *(const float4*)(gam + c);
        float4 bb = *(const float4*)(bet + c);
        float m0 = sm.x * invN, m1 = sm.y * invN, m2 = sm.z * invN, m3 = sm.w * invN;
        sc.x = gg.x * rsqrtf(sq.x * invN - m0 * m0 + BN_EPS);
        sc.y = gg.y * rsqrtf(sq.y * invN - m1 * m1 + BN_EPS);
        sc.z = gg.z * rsqrtf(sq.z * invN - m2 * m2 + BN_EPS);
        sc.w = gg.w * rsqrtf(sq.w * invN - m3 * m3 + BN_EPS);
        sh.x = bb.x - sc.x * m0; sh.y = bb.y - sc.y * m1;
        sh.z = bb.z - sc.z * m2; sh.w = bb.w - sc.w * m3;
    }

    float4 pacc = make_float4(0.f, 0.f, 0.f, 0.f);
    int curg = __ldg(gid + node0);

    for (int node = node0; node < nend; node++) {
        float4 hv = ldh4(feat + (size_t)node * DD + c);
        if (APPLY_BN) hv = bnrelu4(hv, sc, sh);

        int gcur = __ldg(gid + node);
        if (gcur != curg) {
            float* gpd = gp + (size_t)curg * DD + c;
            atomicAdd(gpd + 0, pacc.x); atomicAdd(gpd + 1, pacc.y);
            atomicAdd(gpd + 2, pacc.z); atomicAdd(gpd + 3, pacc.w);
            pacc = make_float4(0.f, 0.f, 0.f, 0.f);
            curg = gcur;
        }
        pacc.x += hv.x; pacc.y += hv.y; pacc.z += hv.z; pacc.w += hv.w;

        float4 acc;
        acc.x = scale * hv.x; acc.y = scale * hv.y;
        acc.z = scale * hv.z; acc.w = scale * hv.w;

        int s = __ldg(rowptr + node), e = __ldg(rowptr + node + 1);
        int i = s;
        for (; i + 3 < e; i += 4) {
            int s0 = __ldg(srcs + i + 0);
            int s1 = __ldg(srcs + i + 1);
            int s2 = __ldg(srcs + i + 2);
            int s3 = __ldg(srcs + i + 3);
            float4 v0 = ldh4(feat + (size_t)s0 * DD + c);
            float4 v1 = ldh4(feat + (size_t)s1 * DD + c);
            float4 v2 = ldh4(feat + (size_t)s2 * DD + c);
            float4 v3 = ldh4(feat + (size_t)s3 * DD + c);
            if (APPLY_BN) {
                v0 = bnrelu4(v0, sc, sh); v1 = bnrelu4(v1, sc, sh);
                v2 = bnrelu4(v2, sc, sh); v3 = bnrelu4(v3, sc, sh);
            }
            acc.x += v0.x + v1.x + v2.x + v3.x;
            acc.y += v0.y + v1.y + v2.y + v3.y;
            acc.z += v0.z + v1.z + v2.z + v3.z;
            acc.w += v0.w + v1.w + v2.w + v3.w;
        }
        for (; i < e; i++) {
            int s0 = __ldg(srcs + i);
            float4 v0 = ldh4(feat + (size_t)s0 * DD + c);
            if (APPLY_BN) v0 = bnrelu4(v0, sc, sh);
            acc.x += v0.x; acc.y += v0.y; acc.z += v0.z; acc.w += v0.w;
        }
        uint2 u;
        u.x = pkh2(acc.x, acc.y);
        u.y = pkh2(acc.z, acc.w);
        *(uint2*)(pooled + (size_t)node * DD + c) = u;
    }
    float* gpd = gp + (size_t)curg * DD + c;
    atomicAdd(gpd + 0, pacc.x); atomicAdd(gpd + 1, pacc.y);
    atomicAdd(gpd + 2, pacc.z); atomicAdd(gpd + 3, pacc.w);
}

// ---------------- fp16 HMMA GEMM: Ch[M,128] = op(A)[M,128] @ W[128,128] + bias ----------------
#define SM_A 0
#define SM_W 32768                  // + ch*16384
#define SM_TOTAL 65536

template<bool APPLY_BN>
__global__ __launch_bounds__(256, 2) void mma_gemm_kernel(
    const __half* __restrict__ A,
    const float* __restrict__ stats_in, const float* __restrict__ gam,
    const float* __restrict__ bet,
    const __half* __restrict__ Wh,
    const float* __restrict__ bias, __half* __restrict__ CoutH,
    float* __restrict__ stats_out) {
    extern __shared__ char smem[];
    __shared__ float scs[2 * DD];
    uint32_t sb = smem_u32(smem);
    int tid = threadIdx.x, wid = tid >> 5, lane = tid & 31;
    int wm = wid >> 2, wn = wid & 3;
    int row0 = blockIdx.x * 128;

    // W loads (global -> smem) via cp.async: 2 chunk tiles of 16KB
    #pragma unroll
    for (int i = 0; i < 8; i++) {
        int slot = i * 256 + tid;          // 0..2047
        int ch = slot >> 10;
        int idx = slot & 1023;
        int row = idx >> 3, c8 = idx & 7;
        cp16(sb + SM_W + ch * 16384 + sw(row, c8),
             Wh + (size_t)row * DD + ch * 64 + c8 * 8);
    }

    if (!APPLY_BN) {
        // A loads via cp.async too (zero staging instructions)
        #pragma unroll
        for (int i = 0; i < 8; i++) {
            int slot = i * 256 + tid;
            int ch = slot >> 10;
            int idx = slot & 1023;
            int row = idx >> 3, c8 = idx & 7;
            int gr = row0 + row;
            bool ok = (gr < N_NODES);
            int grc = ok ? gr : (N_NODES - 1);
            cp16z(sb + SM_A + ch * 16384 + sw(row, c8),
                  A + (size_t)grc * DD + ch * 64 + c8 * 8, ok);
        }
        asm volatile("cp.async.commit_group;" ::: "memory");
        asm volatile("cp.async.wait_group 0;" ::: "memory");
        __syncthreads();
    } else {
        asm volatile("cp.async.commit_group;" ::: "memory");
        if (tid < DD) {
            const float invN = 1.0f / (float)N_NODES;
            float mean = __ldg(stats_in + tid) * invN;
            float var = __ldg(stats_in + DD + tid) * invN - mean * mean;
            float sc = __ldg(gam + tid) * rsqrtf(var + BN_EPS);
            scs[tid] = sc;
            scs[DD + tid] = __ldg(bet + tid) - sc * mean;
        }
        __syncthreads();   // scs visible before A staging reads it
        #pragma unroll
        for (int i = 0; i < 8; i++) {
            int slot = i * 256 + tid;
            int ch = slot >> 10;
            int idx = slot & 1023;
            int row = idx >> 3, c8 = idx & 7;
            int gr = row0 + row;
            int col = ch * 64 + c8 * 8;
            float4 va = make_float4(0.f, 0.f, 0.f, 0.f), vb = va;
            if (gr < N_NODES) {
                const __half* ap = A + (size_t)gr * DD + col;
                va = ldh4(ap);
                vb = ldh4(ap + 4);
            }
            float4 s0 = *(const float4*)(scs + col);
            float4 s1 = *(const float4*)(scs + col + 4);
            float4 t0 = *(const float4*)(scs + DD + col);
            float4 t1 = *(const float4*)(scs + DD + col + 4);
            va = bnrelu4(va, s0, t0);
            vb = bnrelu4(vb, s1, t1);
            uint4 h;
            h.x = pkh2(va.x, va.y);
            h.y = pkh2(va.z, va.w);
            h.z = pkh2(vb.x, vb.y);
            h.w = pkh2(vb.z, vb.w);
            *(uint4*)(smem + SM_A + ch * 16384 + sw(row, c8)) = h;
        }
        asm volatile("cp.async.wait_group 0;" ::: "memory");
        __syncthreads();
    }

    float acc[4][4][4];
    #pragma unroll
    for (int i = 0; i < 4; i++)
        #pragma unroll
        for (int j = 0; j < 4; j++)
            #pragma unroll
            for (int k = 0; k < 4; k++) acc[i][j][k] = 0.f;

    int frow = ((lane >> 3) & 1) * 8 + (lane & 7);
    int fc8base = (lane >> 4);

    #pragma unroll
    for (int ch = 0; ch < 2; ch++) {
        uint32_t ab = sb + SM_A + ch * 16384;
        uint32_t wb = sb + SM_W + ch * 16384;
        #pragma unroll
        for (int ks = 0; ks < 4; ks++) {
            int c8 = ks * 2 + fc8base;
            uint32_t bh[4][2];
            #pragma unroll
            for (int np = 0; np < 2; np++) {
                int n = wn * 32 + np * 16 + frow;
                uint32_t t[4];
                ldm4(t, wb + sw(n, c8));
                bh[np * 2 + 0][0] = t[0]; bh[np * 2 + 1][0] = t[1];
                bh[np * 2 + 0][1] = t[2]; bh[np * 2 + 1][1] = t[3];
            }
            #pragma unroll
            for (int mt = 0; mt < 4; mt++) {
                int r = wm * 64 + mt * 16 + frow;
                uint32_t ah[4];
                ldm4(ah, ab + sw(r, c8));
                #pragma unroll
                for (int nt = 0; nt < 4; nt++)
                    mma16816h(acc[mt][nt], ah, bh[nt]);
            }
        }
    }

    // ---- epilogue: bias, fp16 store, fused column stats (fp32 exact) ----
    float st[4][4];
    #pragma unroll
    for (int nt = 0; nt < 4; nt++)
        #pragma unroll
        for (int k = 0; k < 4; k++) st[nt][k] = 0.f;

    #pragma unroll
    for (int nt = 0; nt < 4; nt++) {
        int col = wn * 32 + nt * 8 + (lane & 3) * 2;
        float2 bs = *(const float2*)(bias + col);
        #pragma unroll
        for (int mt = 0; mt < 4; mt++) {
            int r0g = row0 + wm * 64 + mt * 16 + (lane >> 2);
            float v0 = acc[mt][nt][0] + bs.x;
            float v1 = acc[mt][nt][1] + bs.y;
            float v2 = acc[mt][nt][2] + bs.x;
            float v3 = acc[mt][nt][3] + bs.y;
            if (r0g < N_NODES) {
                *(uint32_t*)(CoutH + (size_t)r0g * DD + col) = pkh2(v0, v1);
                st[nt][0] += v0; st[nt][1] += v1;
                st[nt][2] = fmaf(v0, v0, st[nt][2]);
                st[nt][3] = fmaf(v1, v1, st[nt][3]);
            }
            if (r0g + 8 < N_NODES) {
                *(uint32_t*)(CoutH + (size_t)(r0g + 8) * DD + col) = pkh2(v2, v3);
                st[nt][0] += v2; st[nt][1] += v3;
                st[nt][2] = fmaf(v2, v2, st[nt][2]);
                st[nt][3] = fmaf(v3, v3, st[nt][3]);
            }
        }
    }
    #pragma unroll
    for (int nt = 0; nt < 4; nt++) {
        #pragma unroll
        for (int off = 4; off < 32; off <<= 1) {
            #pragma unroll
            for (int k = 0; k < 4; k++)
                st[nt][k] += __shfl_xor_sync(0xffffffffu, st[nt][k], off);
        }
    }
    if (lane < 4) {
        #pragma unroll
        for (int nt = 0; nt < 4; nt++) {
            int col = wn * 32 + nt * 8 + lane * 2;
            atomicAdd(stats_out + col,          st[nt][0]);
            atomicAdd(stats_out + col + 1,      st[nt][1]);
            atomicAdd(stats_out + DD + col,     st[nt][2]);
            atomicAdd(stats_out + DD + col + 1, st[nt][3]);
        }
    }
}

// ---------------- final pool: BN2(z2)+ReLU summed per graph (fp16 z2) ----------------
__global__ void pool_final_kernel(const __half* __restrict__ z, const float* __restrict__ stats,
                                  const float* __restrict__ g, const float* __restrict__ beta,
                                  const int* __restrict__ gid, float* __restrict__ gp) {
    int tid = threadIdx.x;  // 128
    int r0 = blockIdx.x * POOL_ROWS;
    if (r0 >= N_NODES) return;
    int rend = min(r0 + POOL_ROWS, N_NODES);
    const float invN = 1.0f / (float)N_NODES;
    float mean = __ldg(stats + tid) * invN;
    float var = __ldg(stats + DD + tid) * invN - mean * mean;
    float sc = __ldg(g + tid) * rsqrtf(var + BN_EPS);
    float sh = __ldg(beta + tid) - sc * mean;
    float acc = 0.f;
    int curg = __ldg(gid + r0);
    for (int r = r0; r < rend; r++) {
        float v = __half2float(z[(size_t)r * DD + tid]);
        float hv = fmaxf(0.f, fmaf(sc, v, sh));
        int gcur = __ldg(gid + r);
        if (gcur != curg) {
            atomicAdd(gp + (size_t)curg * DD + tid, acc);
            acc = 0.f;
            curg = gcur;
        }
        acc += hv;
    }
    atomicAdd(gp + (size_t)curg * DD + tid, acc);
}

// ---------------- readout ----------------
__global__ void readout_kernel(const float* __restrict__ gp, const float* __restrict__ Wp,
                               const float* __restrict__ bp, float* __restrict__ out) {
    int g = blockIdx.x;
    int tid = threadIdx.x;  // 128
    int lane = tid & 31, warp = tid >> 5;
    float partial[CC];
    #pragma unroll
    for (int c = 0; c < CC; c++) partial[c] = 0.f;
    for (int l = 0; l < 5; l++) {
        float v = gp[((size_t)l * GG + g) * DD + tid];
        const float* w = Wp + ((size_t)l * DD + tid) * CC;
        #pragma unroll
        for (int c = 0; c < CC; c++) partial[c] = fmaf(v, __ldg(w + c), partial[c]);
    }
    __shared__ float red[4][CC];
    #pragma unroll
    for (int c = 0; c < CC; c++) {
        float v = partial[c];
        #pragma unroll
        for (int off = 16; off; off >>= 1) v += __shfl_down_sync(0xffffffffu, v, off);
        if (lane == 0) red[warp][c] = v;
    }
    __syncthreads();
    if (tid < CC) {
        float s = red[0][tid] + red[1][tid] + red[2][tid] + red[3][tid];
        float b = 0.f;
        #pragma unroll
        for (int l = 0; l < 5; l++) b += __ldg(bp + l * CC + tid);
        out[g * CC + tid] = s + b;
    }
}

// ---------------- host orchestration ----------------
extern "C" void kernel_launch(void* const* d_in, const int* in_sizes, int n_in,
                              void* d_out, int out_size) {
    const float* x     = (const float*)d_in[0];
    const float* eps   = (const float*)d_in[1];
    const float* W1    = (const float*)d_in[2];
    const float* b1    = (const float*)d_in[3];
    const float* g1    = (const float*)d_in[4];
    const float* beta1 = (const float*)d_in[5];
    const float* W2    = (const float*)d_in[6];
    const float* b2    = (const float*)d_in[7];
    const float* g2    = (const float*)d_in[8];
    const float* beta2 = (const float*)d_in[9];
    const float* Wp    = (const float*)d_in[10];
    const float* bp    = (const float*)d_in[11];
    const int* esrc    = (const int*)d_in[12];
    const int* edst    = (const int*)d_in[13];
    const int* gid     = (const int*)d_in[14];
    float* out = (float*)d_out;

    float *gp, *stats;
    __half *pooledh, *z1h, *feath, *wh;
    int *counts, *rowptr, *cursor, *srcsorted, *blocksums;
    cudaGetSymbolAddress((void**)&pooledh, g_pooledh);
    cudaGetSymbolAddress((void**)&z1h, g_z1h);
    cudaGetSymbolAddress((void**)&feath, g_feath);
    cudaGetSymbolAddress((void**)&wh, g_wh);
    cudaGetSymbolAddress((void**)&gp, g_gp);
    cudaGetSymbolAddress((void**)&stats, g_stats);
    cudaGetSymbolAddress((void**)&counts, g_counts);
    cudaGetSymbolAddress((void**)&rowptr, g_rowptr);
    cudaGetSymbolAddress((void**)&cursor, g_cursor);
    cudaGetSymbolAddress((void**)&srcsorted, g_srcsorted);
    cudaGetSymbolAddress((void**)&blocksums, g_blocksums);

    cudaFuncSetAttribute(mma_gemm_kernel<false>,
                         cudaFuncAttributeMaxDynamicSharedMemorySize, SM_TOTAL);
    cudaFuncSetAttribute(mma_gemm_kernel<true>,
                         cudaFuncAttributeMaxDynamicSharedMemorySize, SM_TOTAL);

    zero_kernel<<<256, 256>>>(gp, 5 * GG * DD, stats, NLAYERS * 2 * 2 * DD, counts, N_NODES);
    wprep_kernel<<<dim3(8, 8), 128>>>(W1, W2, wh);
    tohalf_kernel<<<(N_NODES * 32 + 255) / 256, 256>>>(x, feath);
    count_kernel<<<(E_EDGES + 255) / 256, 256>>>(edst, counts);
    scan_pass1<<<SCAN_BLOCKS, 256>>>(counts, blocksums);
    scan_pass2<<<1, 1>>>(blocksums, rowptr);
    scan_pass3<<<SCAN_BLOCKS, 256>>>(counts, blocksums, rowptr, cursor);
    fill_kernel<<<(E_EDGES + 255) / 256, 256>>>(esrc, edst, cursor, srcsorted);

    for (int l = 0; l < NLAYERS; l++) {
        float* st1 = stats + (l * 2 + 0) * 2 * DD;
        float* st2 = stats + (l * 2 + 1) * 2 * DD;

        if (l == 0) {
            spmm_fused_kernel<false><<<SPMM_BLOCKS, 256>>>(
                feath, nullptr, nullptr, nullptr, rowptr, srcsorted, eps, l, gid,
                pooledh, gp + (size_t)l * GG * DD);
        } else {
            float* st2p = stats + ((l - 1) * 2 + 1) * 2 * DD;
            spmm_fused_kernel<true><<<SPMM_BLOCKS, 256>>>(
                feath, st2p, g2 + (l - 1) * DD, beta2 + (l - 1) * DD,
                rowptr, srcsorted, eps, l, gid,
                pooledh, gp + (size_t)l * GG * DD);
        }
        mma_gemm_kernel<false><<<MTILES, 256, SM_TOTAL>>>(
            pooledh, nullptr, nullptr, nullptr,
            wh + (size_t)l * DD * DD, b1 + l * DD, z1h, st1);
        mma_gemm_kernel<true><<<MTILES, 256, SM_TOTAL>>>(
            z1h, st1, g1 + l * DD, beta1 + l * DD,
            wh + (size_t)(4 + l) * DD * DD, b2 + l * DD, feath, st2);
    }
    pool_final_kernel<<<(N_NODES + POOL_ROWS - 1) / POOL_ROWS, 128>>>(
        feath, stats + ((NLAYERS - 1) * 2 + 1) * 2 * DD,
        g2 + (NLAYERS - 1) * DD, beta2 + (NLAYERS - 1) * DD, gid,
        gp + (size_t)NLAYERS * GG * DD);
    readout_kernel<<<GG, 128>>>(gp, Wp, bp, out);
}